// round 1
// baseline (speedup 1.0000x reference)
#include <cuda_runtime.h>

#define NB 4
#define C  128
#define Q  4096   // HS*WS = HR*WR
#define S  64
#define WS_ 64
#define HS_ 64

// Scratch: transposed features, (n, q, c) layout, 8 MB each.
__device__ float g_fr_t[(size_t)NB * Q * C];
__device__ float g_fs_t[(size_t)NB * Q * C];

// Transpose (n, C, Q) -> (n, Q, C) for both fr and fs.
// grid (Q/32, C/32, 2*NB), block (32, 8)
__global__ void transpose_cq(const float* __restrict__ fr,
                             const float* __restrict__ fs) {
    __shared__ float tile[32][33];
    const int which = blockIdx.z >> 2;      // 0 = fr, 1 = fs
    const int n     = blockIdx.z & 3;
    const float* src = which ? fs : fr;
    float* dst       = which ? g_fs_t : g_fr_t;

    const int q0 = blockIdx.x * 32;
    const int c0 = blockIdx.y * 32;

    const float* sp = src + ((size_t)n * C + c0) * Q + q0;
#pragma unroll
    for (int k = 0; k < 4; ++k)
        tile[threadIdx.y + k * 8][threadIdx.x] =
            sp[(size_t)(threadIdx.y + k * 8) * Q + threadIdx.x];
    __syncthreads();

    float* dp = dst + ((size_t)n * Q + q0) * C + c0;
#pragma unroll
    for (int k = 0; k < 4; ++k)
        dp[(size_t)(threadIdx.y + k * 8) * C + threadIdx.x] =
            tile[threadIdx.x][threadIdx.y + k * 8];
}

// One warp per (n, p). Blend the 4 bilinear-corner fs rows in registers,
// then a single 128-length dot with fr_p (one float4 per lane + shfl reduce).
// grid (Q/8, NB), block 256 (8 warps)
__global__ __launch_bounds__(256)
void corr_sample_kernel(const float* __restrict__ grids,
                        const float* __restrict__ mask,
                        float* __restrict__ out) {
    const int lane = threadIdx.x & 31;
    const int warp = threadIdx.x >> 5;
    const int n    = blockIdx.y;
    const int p    = blockIdx.x * 8 + warp;

    // fr_p slice: 4 floats per lane
    const float4 fr4 = *(const float4*)(g_fr_t + ((size_t)n * Q + p) * C + lane * 4);
    const float* fsb = g_fs_t + (size_t)n * Q * C;

    __shared__ float s_out[S][8];
    __shared__ float s_cm[S][8];

    const float* gbase = grids + (size_t)n * S * 2 * Q + p;  // + s*2Q (gx), + s*2Q + Q (gy)
    const float* mbase = mask  + (size_t)n * S * Q + p;      // + s*Q

    for (int s = 0; s < S; ++s) {
        const float gx = __ldg(gbase + (size_t)s * 2 * Q);
        const float gy = __ldg(gbase + (size_t)s * 2 * Q + Q);

        const float ix = gx - 0.5f;
        const float iy = gy - 0.5f;
        const float x0 = floorf(ix);
        const float y0 = floorf(iy);
        const float wx1 = ix - x0;
        const float wy1 = iy - y0;
        const int x0i = (int)x0;
        const int y0i = (int)y0;

        float msum = 0.0f;
        float4 v = make_float4(0.f, 0.f, 0.f, 0.f);

#pragma unroll
        for (int dy = 0; dy < 2; ++dy) {
#pragma unroll
            for (int dx = 0; dx < 2; ++dx) {
                const int xi = x0i + dx;
                const int yi = y0i + dy;
                const bool inb = (xi >= 0) && (xi < WS_) && (yi >= 0) && (yi < HS_);
                const float w = (dx ? wx1 : 1.0f - wx1) * (dy ? wy1 : 1.0f - wy1);
                if (inb) {
                    msum += w;
                    const int q = yi * WS_ + xi;
                    const float4 f =
                        __ldg((const float4*)(fsb + (size_t)q * C + lane * 4));
                    v.x += w * f.x;
                    v.y += w * f.y;
                    v.z += w * f.z;
                    v.w += w * f.w;
                }
            }
        }

        float d = fr4.x * v.x + fr4.y * v.y + fr4.z * v.z + fr4.w * v.w;
#pragma unroll
        for (int o = 16; o; o >>= 1)
            d += __shfl_xor_sync(0xFFFFFFFFu, d, o);

        const float cm = (msum < 0.9999f) ? 0.0f : 1.0f;
        const float mv = __ldg(mbase + (size_t)s * Q);
        if (lane == 0) {
            s_out[s][warp] = d * cm * mv;
            s_cm[s][warp]  = cm * mv;
        }
    }

    __syncthreads();

    // Coalesced-ish writeback: out (n,s,p) then corr_mask (n,s,p)
    float* outp = out + (size_t)n * S * Q + blockIdx.x * 8;
    float* cmp  = outp + (size_t)NB * S * Q;
    for (int t = threadIdx.x; t < S * 8; t += 256) {
        const int s = t >> 3;
        const int j = t & 7;
        outp[(size_t)s * Q + j] = s_out[s][j];
        cmp[(size_t)s * Q + j]  = s_cm[s][j];
    }
}

extern "C" void kernel_launch(void* const* d_in, const int* in_sizes, int n_in,
                              void* d_out, int out_size) {
    const float* fr    = (const float*)d_in[0];
    const float* fs    = (const float*)d_in[1];
    const float* grids = (const float*)d_in[2];
    const float* mask  = (const float*)d_in[3];
    float* out = (float*)d_out;

    transpose_cq<<<dim3(Q / 32, C / 32, 2 * NB), dim3(32, 8)>>>(fr, fs);
    corr_sample_kernel<<<dim3(Q / 8, NB), 256>>>(grids, mask, out);
}